// round 11
// baseline (speedup 1.0000x reference)
#include <cuda_runtime.h>
#include <cuda_fp16.h>
#include <cstdint>

// Problem dims
#define SEQ   256
#define BATCH 32
#define HIDN  1024
#define KDIM  1024
#define MTOT  (SEQ * BATCH)        // 8192
#define BH    (BATCH * HIDN)       // 32768

// ---------------------------------------------------------------------------
// Device-global scratch (no allocation allowed)
// ---------------------------------------------------------------------------
__device__ __align__(16) __half g_Ah[MTOT * KDIM];   // 16 MB (x / y0 in fp16)
__device__ __align__(16) __half g_Wh[HIDN * KDIM];   // 2 MB
__device__ __align__(16) float  g_lin[MTOT * HIDN];  // 32 MB

// ---------------------------------------------------------------------------
// PTX helpers (base sm_103 features only: cp.async, ldmatrix, mma.sync)
// ---------------------------------------------------------------------------
__device__ __forceinline__ uint32_t smem_to_u32(const void* p) {
    uint32_t a;
    asm("{ .reg .u64 t; cvta.to.shared.u64 t, %1; cvt.u32.u64 %0, t; }" : "=r"(a) : "l"(p));
    return a;
}

__device__ __forceinline__ void cp16(uint32_t s, const void* g) {
    asm volatile("cp.async.cg.shared.global [%0], [%1], 16;" :: "r"(s), "l"(g));
}
#define CP_COMMIT() asm volatile("cp.async.commit_group;" ::: "memory")
#define CP_WAIT(n)  asm volatile("cp.async.wait_group %0;" :: "n"(n) : "memory")

__device__ __forceinline__ void ldsm4(uint32_t& r0, uint32_t& r1, uint32_t& r2,
                                      uint32_t& r3, uint32_t addr) {
    asm volatile("ldmatrix.sync.aligned.m8n8.x4.shared.b16 {%0,%1,%2,%3}, [%4];"
        : "=r"(r0), "=r"(r1), "=r"(r2), "=r"(r3) : "r"(addr));
}

__device__ __forceinline__ void mma16816h(float* c, const uint32_t* a, const uint32_t* b) {
    asm volatile(
        "mma.sync.aligned.m16n8k16.row.col.f32.f16.f16.f32 "
        "{%0,%1,%2,%3}, {%4,%5,%6,%7}, {%8,%9}, {%0,%1,%2,%3};"
        : "+f"(c[0]), "+f"(c[1]), "+f"(c[2]), "+f"(c[3])
        : "r"(a[0]), "r"(a[1]), "r"(a[2]), "r"(a[3]), "r"(b[0]), "r"(b[1]));
}

// SW128-style XOR swizzle for 128B rows (8 x 16B chunks), ch in [0,8).
__device__ __forceinline__ uint32_t sw128(int row, int ch) {
    return (uint32_t)((row << 7) | ((ch ^ (row & 7)) << 4));
}

// ---------------------------------------------------------------------------
// Convert fp32 -> fp16 (vectorized by 4)
// ---------------------------------------------------------------------------
__global__ __launch_bounds__(256)
void cvt_fp32_fp16(const float* __restrict__ in, __half* __restrict__ out, int n4)
{
    int i = blockIdx.x * blockDim.x + threadIdx.x;
    if (i >= n4) return;
    float4 v = reinterpret_cast<const float4*>(in)[i];
    union { __half h[4]; uint2 u; } H;
    H.h[0] = __float2half_rn(v.x);
    H.h[1] = __float2half_rn(v.y);
    H.h[2] = __float2half_rn(v.z);
    H.h[3] = __float2half_rn(v.w);
    reinterpret_cast<uint2*>(out)[i] = H.u;
}

// ---------------------------------------------------------------------------
// Single-pass fp16 mma.sync GEMM: C[m,n] = sum_k A[m,k]*W[n,k] + bias[n]
// fp32 register accumulators. CTA tile 128x128, 4 warps, warp tile 64x64.
// K-stage 64, 3-stage cp.async pipeline, SW128-swizzled smem.
// ---------------------------------------------------------------------------
#define STAGES      3
#define BKC         64
#define NKS         (KDIM / BKC)              // 16
#define TILEB       (128 * 128)               // 16384 bytes per tile
#define STAGEB      (2 * TILEB)               // 32768 (A + W)
#define GEMM_SMEM   (STAGES * STAGEB)         // 98304

__device__ __forceinline__ void load_stage(uint32_t sb, int buf, int s,
                                           const __half* __restrict__ A,
                                           const __half* __restrict__ W,
                                           int m0, int n0, int tid)
{
    const int kc = s * BKC;
    const uint32_t base = sb + buf * STAGEB;
#pragma unroll
    for (int it = 0; it < 8; it++) {
        int t = tid + it * 128;          // 0..1023 -> 128 rows x 8 chunks
        int row = t >> 3;
        int ch = t & 7;
        uint32_t soff = sw128(row, ch);
        cp16(base + 0 * TILEB + soff, A + (size_t)(m0 + row) * KDIM + kc + ch * 8);
        cp16(base + 1 * TILEB + soff, W + (size_t)(n0 + row) * KDIM + kc + ch * 8);
    }
}

__global__ __launch_bounds__(128, 2)
void gemm_fp16(const __half* __restrict__ A,
               const __half* __restrict__ W,
               const float* __restrict__ bias,
               float* __restrict__ C)
{
    extern __shared__ __align__(16) char smem[];
    const uint32_t sb = smem_to_u32(smem);
    const int tid = threadIdx.x;
    const int wid = tid >> 5;
    const int lane = tid & 31;
    const int m0 = blockIdx.y * 128;
    const int n0 = blockIdx.x * 128;
    const int wm = (wid >> 1) * 64;      // warp row offset in tile
    const int wn = (wid & 1) * 64;       // warp col offset in tile

    float acc[4][8][4];
#pragma unroll
    for (int i = 0; i < 4; i++)
#pragma unroll
        for (int j = 0; j < 8; j++)
#pragma unroll
            for (int r = 0; r < 4; r++) acc[i][j][r] = 0.0f;

    // ldmatrix lane addressing (fixed per thread)
    const int a_row = lane & 15;                        // + wm + mi*16
    const int a_ch  = lane >> 4;                        // 0/1 within k16
    const int b_row = (lane & 7) + ((lane >> 4) << 3);  // + wn + half*16
    const int b_ch  = (lane >> 3) & 1;

    // Prologue: prefetch stages 0..1
    load_stage(sb, 0, 0, A, W, m0, n0, tid);
    CP_COMMIT();
    load_stage(sb, 1, 1, A, W, m0, n0, tid);
    CP_COMMIT();

    int buf = 0;
    for (int s = 0; s < NKS; s++) {
        CP_WAIT(1);            // stage s resident
        __syncthreads();       // all warps done with the buffer we refill below

        if (s + 2 < NKS) {
            int nbuf = buf + 2; if (nbuf >= STAGES) nbuf -= STAGES;
            load_stage(sb, nbuf, s + 2, A, W, m0, n0, tid);
        }
        CP_COMMIT();           // commit (possibly empty) group to keep count in sync

        const uint32_t st = sb + buf * STAGEB;
#pragma unroll
        for (int kk = 0; kk < 4; kk++) {
            uint32_t af[4][4], bf[8][2];
#pragma unroll
            for (int mi = 0; mi < 4; mi++) {
                uint32_t aoff = sw128(wm + mi * 16 + a_row, kk * 2 + a_ch);
                ldsm4(af[mi][0], af[mi][1], af[mi][2], af[mi][3],
                      st + 0 * TILEB + aoff);
            }
#pragma unroll
            for (int half = 0; half < 4; half++) {
                uint32_t boff = sw128(wn + b_row + half * 16, kk * 2 + b_ch);
                ldsm4(bf[half * 2][0], bf[half * 2][1],
                      bf[half * 2 + 1][0], bf[half * 2 + 1][1],
                      st + 1 * TILEB + boff);
            }
#pragma unroll
            for (int mi = 0; mi < 4; mi++)
#pragma unroll
                for (int ni = 0; ni < 8; ni++)
                    mma16816h(acc[mi][ni], af[mi], bf[ni]);
        }
        buf++; if (buf >= STAGES) buf -= STAGES;
    }

    // Epilogue: add bias, store fp32
    const int er = lane >> 2;
    const int ec = (lane & 3) * 2;
#pragma unroll
    for (int mi = 0; mi < 4; mi++) {
        const int r = m0 + wm + mi * 16 + er;
#pragma unroll
        for (int ni = 0; ni < 8; ni++) {
            const int c = n0 + wn + ni * 8 + ec;
            const float b0 = __ldg(bias + c);
            const float b1 = __ldg(bias + c + 1);
            float2 v0 = {acc[mi][ni][0] + b0, acc[mi][ni][1] + b1};
            float2 v1 = {acc[mi][ni][2] + b0, acc[mi][ni][3] + b1};
            *reinterpret_cast<float2*>(C + (size_t)r * HIDN + c) = v0;
            *reinterpret_cast<float2*>(C + (size_t)(r + 8) * HIDN + c) = v1;
        }
    }
}

// ---------------------------------------------------------------------------
// IndRNN scan: 8 blocks of 32 steps, 4 rotating buffers, prefetch 3 ahead
// (fully unrolled so buffers stay in registers). 256 thr x 128 blocks.
// ---------------------------------------------------------------------------
__global__ __launch_bounds__(256)
void indrnn_scan_f32(const float* __restrict__ lin, const float* __restrict__ rec,
                     float* __restrict__ y, float* __restrict__ hid_out, int off)
{
    const int idx = blockIdx.x * 256 + threadIdx.x;
    const int h = idx & (HIDN - 1);
    const int b = idx >> 10;
    const float r = rec[h];
    const float* p = lin + idx;
    float* q = y + idx;

    float buf[4][32];
#pragma unroll
    for (int w = 0; w < 3; w++)
#pragma unroll
        for (int u = 0; u < 32; u++)
            buf[w][u] = __ldcs(p + (size_t)(w * 32 + u) * BH);

    float hv = 0.0f;
#pragma unroll
    for (int blk = 0; blk < 8; blk++) {
        if (blk + 3 < 8) {
#pragma unroll
            for (int u = 0; u < 32; u++)
                buf[(blk + 3) & 3][u] = __ldcs(p + (size_t)((blk + 3) * 32 + u) * BH);
        }
#pragma unroll
        for (int u = 0; u < 32; u++) {
            hv = fmaxf(fmaf(r, hv, buf[blk & 3][u]), 0.0f);
            q[(size_t)(blk * 32 + u) * BH] = hv;
        }
    }
    hid_out[(size_t)b * (2 * HIDN) + off + h] = hv;
}

// Variant writing fp16 directly (feeds the next layer's GEMM).
__global__ __launch_bounds__(256)
void indrnn_scan_h(const float* __restrict__ lin, const float* __restrict__ rec,
                   __half* __restrict__ yh, float* __restrict__ hid_out, int off)
{
    const int idx = blockIdx.x * 256 + threadIdx.x;
    const int h = idx & (HIDN - 1);
    const int b = idx >> 10;
    const float r = rec[h];
    const float* p = lin + idx;

    float buf[4][32];
#pragma unroll
    for (int w = 0; w < 3; w++)
#pragma unroll
        for (int u = 0; u < 32; u++)
            buf[w][u] = __ldcs(p + (size_t)(w * 32 + u) * BH);

    float hv = 0.0f;
#pragma unroll
    for (int blk = 0; blk < 8; blk++) {
        if (blk + 3 < 8) {
#pragma unroll
            for (int u = 0; u < 32; u++)
                buf[(blk + 3) & 3][u] = __ldcs(p + (size_t)((blk + 3) * 32 + u) * BH);
        }
#pragma unroll
        for (int u = 0; u < 32; u++) {
            hv = fmaxf(fmaf(r, hv, buf[blk & 3][u]), 0.0f);
            yh[(size_t)(blk * 32 + u) * BH + idx] = __float2half_rn(hv);
        }
    }
    hid_out[(size_t)b * (2 * HIDN) + off + h] = hv;
}

// ---------------------------------------------------------------------------
// kernel_launch
// Inputs: x (S,B,IN), w0 (H,IN), b0 (H), w1 (H,H), b1 (H), rec (2,H)
// Output: y1 (S,B,H) then hiddens (B, 2H)
// ---------------------------------------------------------------------------
extern "C" void kernel_launch(void* const* d_in, const int* in_sizes, int n_in,
                              void* d_out, int out_size)
{
    const float* x   = (const float*)d_in[0];
    const float* w0  = (const float*)d_in[1];
    const float* b0  = (const float*)d_in[2];
    const float* w1  = (const float*)d_in[3];
    const float* b1  = (const float*)d_in[4];
    const float* rec = (const float*)d_in[5];

    float* out     = (float*)d_out;
    float* y1_out  = out;
    float* hid_out = out + (size_t)MTOT * HIDN;

    __half *Ah, *Wh;
    float* lin;
    cudaGetSymbolAddress((void**)&Ah, g_Ah);
    cudaGetSymbolAddress((void**)&Wh, g_Wh);
    cudaGetSymbolAddress((void**)&lin, g_lin);

    cudaFuncSetAttribute(gemm_fp16, cudaFuncAttributeMaxDynamicSharedMemorySize, GEMM_SMEM);

    const int nX4 = MTOT * KDIM / 4;
    const int nW4 = HIDN * KDIM / 4;

    dim3 ggrid(HIDN / 128, MTOT / 128);  // (8, 64)
    dim3 sgrid(BH / 256);                // 128 blocks

    // Layer 0
    cvt_fp32_fp16<<<(nX4 + 255) / 256, 256>>>(x, Ah, nX4);
    cvt_fp32_fp16<<<(nW4 + 255) / 256, 256>>>(w0, Wh, nW4);
    gemm_fp16<<<ggrid, 128, GEMM_SMEM>>>(Ah, Wh, b0, lin);
    indrnn_scan_h<<<sgrid, 256>>>(lin, rec, Ah, hid_out, 0);

    // Layer 1
    cvt_fp32_fp16<<<(nW4 + 255) / 256, 256>>>(w1, Wh, nW4);
    gemm_fp16<<<ggrid, 128, GEMM_SMEM>>>(Ah, Wh, b1, lin);
    indrnn_scan_f32<<<sgrid, 256>>>(lin, rec + HIDN, y1_out, hid_out, HIDN);
}

// round 12
// speedup vs baseline: 1.0474x; 1.0474x over previous
#include <cuda_runtime.h>
#include <cuda_fp16.h>
#include <cstdint>

// Problem dims
#define SEQ   256
#define BATCH 32
#define HIDN  1024
#define KDIM  1024
#define MTOT  (SEQ * BATCH)        // 8192
#define BH    (BATCH * HIDN)       // 32768

// ---------------------------------------------------------------------------
// Device-global scratch (no allocation allowed)
// ---------------------------------------------------------------------------
__device__ __align__(16) __half g_Ah[MTOT * KDIM];   // 16 MB (x / y0 in fp16)
__device__ __align__(16) __half g_Wh[HIDN * KDIM];   // 2 MB
__device__ __align__(16) float  g_lin[MTOT * HIDN];  // 32 MB

// ---------------------------------------------------------------------------
// PTX helpers (base sm_103 features only: cp.async, ldmatrix, mma.sync)
// ---------------------------------------------------------------------------
__device__ __forceinline__ uint32_t smem_to_u32(const void* p) {
    uint32_t a;
    asm("{ .reg .u64 t; cvta.to.shared.u64 t, %1; cvt.u32.u64 %0, t; }" : "=r"(a) : "l"(p));
    return a;
}

__device__ __forceinline__ void cp16(uint32_t s, const void* g) {
    asm volatile("cp.async.cg.shared.global [%0], [%1], 16;" :: "r"(s), "l"(g));
}
#define CP_COMMIT() asm volatile("cp.async.commit_group;" ::: "memory")
#define CP_WAIT(n)  asm volatile("cp.async.wait_group %0;" :: "n"(n) : "memory")

__device__ __forceinline__ void ldsm4(uint32_t& r0, uint32_t& r1, uint32_t& r2,
                                      uint32_t& r3, uint32_t addr) {
    asm volatile("ldmatrix.sync.aligned.m8n8.x4.shared.b16 {%0,%1,%2,%3}, [%4];"
        : "=r"(r0), "=r"(r1), "=r"(r2), "=r"(r3) : "r"(addr));
}

__device__ __forceinline__ void mma16816h(float* c, const uint32_t* a, const uint32_t* b) {
    asm volatile(
        "mma.sync.aligned.m16n8k16.row.col.f32.f16.f16.f32 "
        "{%0,%1,%2,%3}, {%4,%5,%6,%7}, {%8,%9}, {%0,%1,%2,%3};"
        : "+f"(c[0]), "+f"(c[1]), "+f"(c[2]), "+f"(c[3])
        : "r"(a[0]), "r"(a[1]), "r"(a[2]), "r"(a[3]), "r"(b[0]), "r"(b[1]));
}

// XOR swizzle for 64B rows (4x 16B chunks): conflict-free for ldmatrix phases
// and cp.async store phases. period = 8 rows.
__device__ __forceinline__ uint32_t sw_off(int row, int ch) {
    return (uint32_t)((row << 6) + ((ch ^ ((row >> 1) & 3)) << 4));
}

// ---------------------------------------------------------------------------
// Convert fp32 -> fp16 (vectorized by 4)
// ---------------------------------------------------------------------------
__global__ __launch_bounds__(256)
void cvt_fp32_fp16(const float* __restrict__ in, __half* __restrict__ out, int n4)
{
    int i = blockIdx.x * blockDim.x + threadIdx.x;
    if (i >= n4) return;
    float4 v = reinterpret_cast<const float4*>(in)[i];
    union { __half h[4]; uint2 u; } H;
    H.h[0] = __float2half_rn(v.x);
    H.h[1] = __float2half_rn(v.y);
    H.h[2] = __float2half_rn(v.z);
    H.h[3] = __float2half_rn(v.w);
    reinterpret_cast<uint2*>(out)[i] = H.u;
}

// ---------------------------------------------------------------------------
// Single-pass fp16 mma.sync GEMM: C[m,n] = sum_k A[m,k]*W[n,k] + bias[n]
// fp32 register accumulators. CTA tile 128x128, 4 warps, warp tile 64x64.
// K-stage 32, 4-stage cp.async pipeline, XOR-swizzled smem. (R10 config)
// ---------------------------------------------------------------------------
#define STAGES      4
#define BKC         32
#define NKS         (KDIM / BKC)              // 32
#define TILEB       (128 * 64)                // 8192 bytes per tile
#define STAGEB      (2 * TILEB)               // 16384 (A + W)
#define GEMM_SMEM   (STAGES * STAGEB)         // 65536

__device__ __forceinline__ void load_stage(uint32_t sb, int buf, int s,
                                           const __half* __restrict__ A,
                                           const __half* __restrict__ W,
                                           int m0, int n0, int tid)
{
    const int kc = s * BKC;
    const uint32_t base = sb + buf * STAGEB;
#pragma unroll
    for (int it = 0; it < 4; it++) {
        int t = tid + it * 128;          // 0..511 -> 128 rows x 4 chunks
        int row = t >> 2;
        int ch = t & 3;
        uint32_t soff = sw_off(row, ch);
        cp16(base + 0 * TILEB + soff, A + (size_t)(m0 + row) * KDIM + kc + ch * 8);
        cp16(base + 1 * TILEB + soff, W + (size_t)(n0 + row) * KDIM + kc + ch * 8);
    }
}

__global__ __launch_bounds__(128, 2)
void gemm_fp16(const __half* __restrict__ A,
               const __half* __restrict__ W,
               const float* __restrict__ bias,
               float* __restrict__ C)
{
    extern __shared__ __align__(16) char smem[];
    const uint32_t sb = smem_to_u32(smem);
    const int tid = threadIdx.x;
    const int wid = tid >> 5;
    const int lane = tid & 31;
    const int m0 = blockIdx.y * 128;
    const int n0 = blockIdx.x * 128;
    const int wm = (wid >> 1) * 64;      // warp row offset in tile
    const int wn = (wid & 1) * 64;       // warp col offset in tile

    float acc[4][8][4];
#pragma unroll
    for (int i = 0; i < 4; i++)
#pragma unroll
        for (int j = 0; j < 8; j++)
#pragma unroll
            for (int r = 0; r < 4; r++) acc[i][j][r] = 0.0f;

    // ldmatrix lane addressing (fixed per thread)
    const int a_row = lane & 15;                        // + wm + mi*16
    const int a_ch  = lane >> 4;                        // 0/1 within k16
    const int b_row = (lane & 7) + ((lane >> 4) << 3);  // + wn + half*16
    const int b_ch  = (lane >> 3) & 1;

    // Prologue: prefetch stages 0..2
    load_stage(sb, 0, 0, A, W, m0, n0, tid);
    CP_COMMIT();
    load_stage(sb, 1, 1, A, W, m0, n0, tid);
    CP_COMMIT();
    load_stage(sb, 2, 2, A, W, m0, n0, tid);
    CP_COMMIT();

    int buf = 0;
    for (int s = 0; s < NKS; s++) {
        CP_WAIT(2);            // stage s resident
        __syncthreads();       // all warps done with the buffer we refill below

        if (s + 3 < NKS) {
            int nbuf = buf + 3; if (nbuf >= STAGES) nbuf -= STAGES;
            load_stage(sb, nbuf, s + 3, A, W, m0, n0, tid);
        }
        CP_COMMIT();           // commit (possibly empty) group to keep count in sync

        const uint32_t st = sb + buf * STAGEB;
#pragma unroll
        for (int kk = 0; kk < 2; kk++) {
            uint32_t af[4][4], bf[8][2];
#pragma unroll
            for (int mi = 0; mi < 4; mi++) {
                uint32_t aoff = sw_off(wm + mi * 16 + a_row, kk * 2 + a_ch);
                ldsm4(af[mi][0], af[mi][1], af[mi][2], af[mi][3],
                      st + 0 * TILEB + aoff);
            }
#pragma unroll
            for (int half = 0; half < 4; half++) {
                uint32_t boff = sw_off(wn + b_row + half * 16, kk * 2 + b_ch);
                ldsm4(bf[half * 2][0], bf[half * 2][1],
                      bf[half * 2 + 1][0], bf[half * 2 + 1][1],
                      st + 1 * TILEB + boff);
            }
#pragma unroll
            for (int mi = 0; mi < 4; mi++)
#pragma unroll
                for (int ni = 0; ni < 8; ni++)
                    mma16816h(acc[mi][ni], af[mi], bf[ni]);
        }
        buf++; if (buf >= STAGES) buf -= STAGES;
    }

    // Epilogue: add bias, store fp32
    const int er = lane >> 2;
    const int ec = (lane & 3) * 2;
#pragma unroll
    for (int mi = 0; mi < 4; mi++) {
        const int r = m0 + wm + mi * 16 + er;
#pragma unroll
        for (int ni = 0; ni < 8; ni++) {
            const int c = n0 + wn + ni * 8 + ec;
            const float b0 = __ldg(bias + c);
            const float b1 = __ldg(bias + c + 1);
            float2 v0 = {acc[mi][ni][0] + b0, acc[mi][ni][1] + b1};
            float2 v1 = {acc[mi][ni][2] + b0, acc[mi][ni][3] + b1};
            *reinterpret_cast<float2*>(C + (size_t)r * HIDN + c) = v0;
            *reinterpret_cast<float2*>(C + (size_t)(r + 8) * HIDN + c) = v1;
        }
    }
}

// ---------------------------------------------------------------------------
// IndRNN scan: 8 blocks of 32 steps, 4 rotating buffers, prefetch 3 ahead
// (fully unrolled so buffers stay in registers). 256 thr x 128 blocks. (R11)
// ---------------------------------------------------------------------------
__global__ __launch_bounds__(256)
void indrnn_scan_f32(const float* __restrict__ lin, const float* __restrict__ rec,
                     float* __restrict__ y, float* __restrict__ hid_out, int off)
{
    const int idx = blockIdx.x * 256 + threadIdx.x;
    const int h = idx & (HIDN - 1);
    const int b = idx >> 10;
    const float r = rec[h];
    const float* p = lin + idx;
    float* q = y + idx;

    float buf[4][32];
#pragma unroll
    for (int w = 0; w < 3; w++)
#pragma unroll
        for (int u = 0; u < 32; u++)
            buf[w][u] = __ldcs(p + (size_t)(w * 32 + u) * BH);

    float hv = 0.0f;
#pragma unroll
    for (int blk = 0; blk < 8; blk++) {
        if (blk + 3 < 8) {
#pragma unroll
            for (int u = 0; u < 32; u++)
                buf[(blk + 3) & 3][u] = __ldcs(p + (size_t)((blk + 3) * 32 + u) * BH);
        }
#pragma unroll
        for (int u = 0; u < 32; u++) {
            hv = fmaxf(fmaf(r, hv, buf[blk & 3][u]), 0.0f);
            q[(size_t)(blk * 32 + u) * BH] = hv;
        }
    }
    hid_out[(size_t)b * (2 * HIDN) + off + h] = hv;
}

// Variant writing fp16 directly (feeds the next layer's GEMM).
__global__ __launch_bounds__(256)
void indrnn_scan_h(const float* __restrict__ lin, const float* __restrict__ rec,
                   __half* __restrict__ yh, float* __restrict__ hid_out, int off)
{
    const int idx = blockIdx.x * 256 + threadIdx.x;
    const int h = idx & (HIDN - 1);
    const int b = idx >> 10;
    const float r = rec[h];
    const float* p = lin + idx;

    float buf[4][32];
#pragma unroll
    for (int w = 0; w < 3; w++)
#pragma unroll
        for (int u = 0; u < 32; u++)
            buf[w][u] = __ldcs(p + (size_t)(w * 32 + u) * BH);

    float hv = 0.0f;
#pragma unroll
    for (int blk = 0; blk < 8; blk++) {
        if (blk + 3 < 8) {
#pragma unroll
            for (int u = 0; u < 32; u++)
                buf[(blk + 3) & 3][u] = __ldcs(p + (size_t)((blk + 3) * 32 + u) * BH);
        }
#pragma unroll
        for (int u = 0; u < 32; u++) {
            hv = fmaxf(fmaf(r, hv, buf[blk & 3][u]), 0.0f);
            yh[(size_t)(blk * 32 + u) * BH + idx] = __float2half_rn(hv);
        }
    }
    hid_out[(size_t)b * (2 * HIDN) + off + h] = hv;
}

// ---------------------------------------------------------------------------
// kernel_launch
// Inputs: x (S,B,IN), w0 (H,IN), b0 (H), w1 (H,H), b1 (H), rec (2,H)
// Output: y1 (S,B,H) then hiddens (B, 2H)
// ---------------------------------------------------------------------------
extern "C" void kernel_launch(void* const* d_in, const int* in_sizes, int n_in,
                              void* d_out, int out_size)
{
    const float* x   = (const float*)d_in[0];
    const float* w0  = (const float*)d_in[1];
    const float* b0  = (const float*)d_in[2];
    const float* w1  = (const float*)d_in[3];
    const float* b1  = (const float*)d_in[4];
    const float* rec = (const float*)d_in[5];

    float* out     = (float*)d_out;
    float* y1_out  = out;
    float* hid_out = out + (size_t)MTOT * HIDN;

    __half *Ah, *Wh;
    float* lin;
    cudaGetSymbolAddress((void**)&Ah, g_Ah);
    cudaGetSymbolAddress((void**)&Wh, g_Wh);
    cudaGetSymbolAddress((void**)&lin, g_lin);

    cudaFuncSetAttribute(gemm_fp16, cudaFuncAttributeMaxDynamicSharedMemorySize, GEMM_SMEM);

    const int nX4 = MTOT * KDIM / 4;
    const int nW4 = HIDN * KDIM / 4;

    dim3 ggrid(HIDN / 128, MTOT / 128);  // (8, 64)
    dim3 sgrid(BH / 256);                // 128 blocks

    // Layer 0
    cvt_fp32_fp16<<<(nX4 + 255) / 256, 256>>>(x, Ah, nX4);
    cvt_fp32_fp16<<<(nW4 + 255) / 256, 256>>>(w0, Wh, nW4);
    gemm_fp16<<<ggrid, 128, GEMM_SMEM>>>(Ah, Wh, b0, lin);
    indrnn_scan_h<<<sgrid, 256>>>(lin, rec, Ah, hid_out, 0);

    // Layer 1
    cvt_fp32_fp16<<<(nW4 + 255) / 256, 256>>>(w1, Wh, nW4);
    gemm_fp16<<<ggrid, 128, GEMM_SMEM>>>(Ah, Wh, b1, lin);
    indrnn_scan_f32<<<sgrid, 256>>>(lin, rec + HIDN, y1_out, hid_out, HIDN);
}

// round 15
// speedup vs baseline: 1.0511x; 1.0035x over previous
#include <cuda_runtime.h>
#include <cuda_fp16.h>
#include <cstdint>

// Problem dims
#define SEQ   256
#define BATCH 32
#define HIDN  1024
#define KDIM  1024
#define MTOT  (SEQ * BATCH)        // 8192
#define BH    (BATCH * HIDN)       // 32768

// ---------------------------------------------------------------------------
// Device-global scratch (no allocation allowed)
// ---------------------------------------------------------------------------
__device__ __align__(16) __half g_Ah  [MTOT * KDIM];   // 16 MB (x / y0 in fp16)
__device__ __align__(16) __half g_Wh0 [HIDN * KDIM];   // 2 MB
__device__ __align__(16) __half g_Wh1 [HIDN * KDIM];   // 2 MB
__device__ __align__(16) __half g_linh[MTOT * HIDN];   // 16 MB (fp16 lin)

// ---------------------------------------------------------------------------
// PTX helpers (base sm_103 features only: cp.async, ldmatrix, mma.sync)
// ---------------------------------------------------------------------------
__device__ __forceinline__ uint32_t smem_to_u32(const void* p) {
    uint32_t a;
    asm("{ .reg .u64 t; cvta.to.shared.u64 t, %1; cvt.u32.u64 %0, t; }" : "=r"(a) : "l"(p));
    return a;
}

__device__ __forceinline__ void cp16(uint32_t s, const void* g) {
    asm volatile("cp.async.cg.shared.global [%0], [%1], 16;" :: "r"(s), "l"(g));
}
#define CP_COMMIT() asm volatile("cp.async.commit_group;" ::: "memory")
#define CP_WAIT(n)  asm volatile("cp.async.wait_group %0;" :: "n"(n) : "memory")

__device__ __forceinline__ void ldsm4(uint32_t& r0, uint32_t& r1, uint32_t& r2,
                                      uint32_t& r3, uint32_t addr) {
    asm volatile("ldmatrix.sync.aligned.m8n8.x4.shared.b16 {%0,%1,%2,%3}, [%4];"
        : "=r"(r0), "=r"(r1), "=r"(r2), "=r"(r3) : "r"(addr));
}

__device__ __forceinline__ void mma16816h(float* c, const uint32_t* a, const uint32_t* b) {
    asm volatile(
        "mma.sync.aligned.m16n8k16.row.col.f32.f16.f16.f32 "
        "{%0,%1,%2,%3}, {%4,%5,%6,%7}, {%8,%9}, {%0,%1,%2,%3};"
        : "+f"(c[0]), "+f"(c[1]), "+f"(c[2]), "+f"(c[3])
        : "r"(a[0]), "r"(a[1]), "r"(a[2]), "r"(a[3]), "r"(b[0]), "r"(b[1]));
}

// XOR swizzle for 64B rows (4x 16B chunks): conflict-free for ldmatrix phases
// and cp.async store phases. period = 8 rows.
__device__ __forceinline__ uint32_t sw_off(int row, int ch) {
    return (uint32_t)((row << 6) + ((ch ^ ((row >> 1) & 3)) << 4));
}

// ---------------------------------------------------------------------------
// Convert fp32 -> fp16 (vectorized by 4)
// ---------------------------------------------------------------------------
__global__ __launch_bounds__(256)
void cvt_fp32_fp16(const float* __restrict__ in, __half* __restrict__ out, int n4)
{
    int i = blockIdx.x * blockDim.x + threadIdx.x;
    if (i >= n4) return;
    float4 v = reinterpret_cast<const float4*>(in)[i];
    union { __half h[4]; uint2 u; } H;
    H.h[0] = __float2half_rn(v.x);
    H.h[1] = __float2half_rn(v.y);
    H.h[2] = __float2half_rn(v.z);
    H.h[3] = __float2half_rn(v.w);
    reinterpret_cast<uint2*>(out)[i] = H.u;
}

// ---------------------------------------------------------------------------
// Single-pass fp16 mma.sync GEMM: C[m,n] = (half) sum_k A[m,k]*W[n,k] + bias[n]
// fp32 register accumulators, fp16 output. CTA tile 128x128, 4 warps,
// warp tile 64x64, K-stage 32, 4-stage cp.async pipeline, XOR-swizzled smem.
// ---------------------------------------------------------------------------
#define STAGES      4
#define BKC         32
#define NKS         (KDIM / BKC)              // 32
#define TILEB       (128 * 64)                // 8192 bytes per tile
#define STAGEB      (2 * TILEB)               // 16384 (A + W)
#define GEMM_SMEM   (STAGES * STAGEB)         // 65536

__device__ __forceinline__ void load_stage(uint32_t sb, int buf, int s,
                                           const __half* __restrict__ A,
                                           const __half* __restrict__ W,
                                           int m0, int n0, int tid)
{
    const int kc = s * BKC;
    const uint32_t base = sb + buf * STAGEB;
#pragma unroll
    for (int it = 0; it < 4; it++) {
        int t = tid + it * 128;          // 0..511 -> 128 rows x 4 chunks
        int row = t >> 2;
        int ch = t & 3;
        uint32_t soff = sw_off(row, ch);
        cp16(base + 0 * TILEB + soff, A + (size_t)(m0 + row) * KDIM + kc + ch * 8);
        cp16(base + 1 * TILEB + soff, W + (size_t)(n0 + row) * KDIM + kc + ch * 8);
    }
}

__global__ __launch_bounds__(128, 2)
void gemm_fp16(const __half* __restrict__ A,
               const __half* __restrict__ W,
               const float* __restrict__ bias,
               __half* __restrict__ C)
{
    extern __shared__ __align__(16) char smem[];
    const uint32_t sb = smem_to_u32(smem);
    const int tid = threadIdx.x;
    const int wid = tid >> 5;
    const int lane = tid & 31;
    const int m0 = blockIdx.y * 128;
    const int n0 = blockIdx.x * 128;
    const int wm = (wid >> 1) * 64;      // warp row offset in tile
    const int wn = (wid & 1) * 64;       // warp col offset in tile

    float acc[4][8][4];
#pragma unroll
    for (int i = 0; i < 4; i++)
#pragma unroll
        for (int j = 0; j < 8; j++)
#pragma unroll
            for (int r = 0; r < 4; r++) acc[i][j][r] = 0.0f;

    // ldmatrix lane addressing (fixed per thread)
    const int a_row = lane & 15;                        // + wm + mi*16
    const int a_ch  = lane >> 4;                        // 0/1 within k16
    const int b_row = (lane & 7) + ((lane >> 4) << 3);  // + wn + half*16
    const int b_ch  = (lane >> 3) & 1;

    // Prologue: prefetch stages 0..2
    load_stage(sb, 0, 0, A, W, m0, n0, tid);
    CP_COMMIT();
    load_stage(sb, 1, 1, A, W, m0, n0, tid);
    CP_COMMIT();
    load_stage(sb, 2, 2, A, W, m0, n0, tid);
    CP_COMMIT();

    int buf = 0;
    for (int s = 0; s < NKS; s++) {
        CP_WAIT(2);            // stage s resident
        __syncthreads();       // all warps done with the buffer we refill below

        if (s + 3 < NKS) {
            int nbuf = buf + 3; if (nbuf >= STAGES) nbuf -= STAGES;
            load_stage(sb, nbuf, s + 3, A, W, m0, n0, tid);
        }
        CP_COMMIT();           // commit (possibly empty) group to keep count in sync

        const uint32_t st = sb + buf * STAGEB;
#pragma unroll
        for (int kk = 0; kk < 2; kk++) {
            uint32_t af[4][4], bf[8][2];
#pragma unroll
            for (int mi = 0; mi < 4; mi++) {
                uint32_t aoff = sw_off(wm + mi * 16 + a_row, kk * 2 + a_ch);
                ldsm4(af[mi][0], af[mi][1], af[mi][2], af[mi][3],
                      st + 0 * TILEB + aoff);
            }
#pragma unroll
            for (int half = 0; half < 4; half++) {
                uint32_t boff = sw_off(wn + b_row + half * 16, kk * 2 + b_ch);
                ldsm4(bf[half * 2][0], bf[half * 2][1],
                      bf[half * 2 + 1][0], bf[half * 2 + 1][1],
                      st + 1 * TILEB + boff);
            }
#pragma unroll
            for (int mi = 0; mi < 4; mi++)
#pragma unroll
                for (int ni = 0; ni < 8; ni++)
                    mma16816h(acc[mi][ni], af[mi], bf[ni]);
        }
        buf++; if (buf >= STAGES) buf -= STAGES;
    }

    // Epilogue: add bias (fp32), store fp16
    const int er = lane >> 2;
    const int ec = (lane & 3) * 2;
#pragma unroll
    for (int mi = 0; mi < 4; mi++) {
        const int r = m0 + wm + mi * 16 + er;
#pragma unroll
        for (int ni = 0; ni < 8; ni++) {
            const int c = n0 + wn + ni * 8 + ec;
            const float b0 = __ldg(bias + c);
            const float b1 = __ldg(bias + c + 1);
            __half2 v0 = __floats2half2_rn(acc[mi][ni][0] + b0, acc[mi][ni][1] + b1);
            __half2 v1 = __floats2half2_rn(acc[mi][ni][2] + b0, acc[mi][ni][3] + b1);
            *reinterpret_cast<__half2*>(C + (size_t)r * HIDN + c) = v0;
            *reinterpret_cast<__half2*>(C + (size_t)(r + 8) * HIDN + c) = v1;
        }
    }
}

// ---------------------------------------------------------------------------
// IndRNN scan: fp16 lin input. 8 blocks of 32 steps, 4 rotating buffers,
// prefetch 3 ahead (fully unrolled). 256 thr x 128 blocks.
// ---------------------------------------------------------------------------
__global__ __launch_bounds__(256)
void indrnn_scan_f32(const __half* __restrict__ lin, const float* __restrict__ rec,
                     float* __restrict__ y, float* __restrict__ hid_out, int off)
{
    const int idx = blockIdx.x * 256 + threadIdx.x;
    const int h = idx & (HIDN - 1);
    const int b = idx >> 10;
    const float r = rec[h];
    const __half* p = lin + idx;
    float* q = y + idx;

    float buf[4][32];
#pragma unroll
    for (int w = 0; w < 3; w++)
#pragma unroll
        for (int u = 0; u < 32; u++)
            buf[w][u] = __half2float(__ldcs(p + (size_t)(w * 32 + u) * BH));

    float hv = 0.0f;
#pragma unroll
    for (int blk = 0; blk < 8; blk++) {
        if (blk + 3 < 8) {
#pragma unroll
            for (int u = 0; u < 32; u++)
                buf[(blk + 3) & 3][u] =
                    __half2float(__ldcs(p + (size_t)((blk + 3) * 32 + u) * BH));
        }
#pragma unroll
        for (int u = 0; u < 32; u++) {
            hv = fmaxf(fmaf(r, hv, buf[blk & 3][u]), 0.0f);
            q[(size_t)(blk * 32 + u) * BH] = hv;
        }
    }
    hid_out[(size_t)b * (2 * HIDN) + off + h] = hv;
}

// Variant writing fp16 directly (feeds the next layer's GEMM).
__global__ __launch_bounds__(256)
void indrnn_scan_h(const __half* __restrict__ lin, const float* __restrict__ rec,
                   __half* __restrict__ yh, float* __restrict__ hid_out, int off)
{
    const int idx = blockIdx.x * 256 + threadIdx.x;
    const int h = idx & (HIDN - 1);
    const int b = idx >> 10;
    const float r = rec[h];
    const __half* p = lin + idx;

    float buf[4][32];
#pragma unroll
    for (int w = 0; w < 3; w++)
#pragma unroll
        for (int u = 0; u < 32; u++)
            buf[w][u] = __half2float(__ldcs(p + (size_t)(w * 32 + u) * BH));

    float hv = 0.0f;
#pragma unroll
    for (int blk = 0; blk < 8; blk++) {
        if (blk + 3 < 8) {
#pragma unroll
            for (int u = 0; u < 32; u++)
                buf[(blk + 3) & 3][u] =
                    __half2float(__ldcs(p + (size_t)((blk + 3) * 32 + u) * BH));
        }
#pragma unroll
        for (int u = 0; u < 32; u++) {
            hv = fmaxf(fmaf(r, hv, buf[blk & 3][u]), 0.0f);
            yh[(size_t)(blk * 32 + u) * BH + idx] = __float2half_rn(hv);
        }
    }
    hid_out[(size_t)b * (2 * HIDN) + off + h] = hv;
}

// ---------------------------------------------------------------------------
// kernel_launch
// Inputs: x (S,B,IN), w0 (H,IN), b0 (H), w1 (H,H), b1 (H), rec (2,H)
// Output: y1 (S,B,H) then hiddens (B, 2H)
// ---------------------------------------------------------------------------
extern "C" void kernel_launch(void* const* d_in, const int* in_sizes, int n_in,
                              void* d_out, int out_size)
{
    const float* x   = (const float*)d_in[0];
    const float* w0  = (const float*)d_in[1];
    const float* b0  = (const float*)d_in[2];
    const float* w1  = (const float*)d_in[3];
    const float* b1  = (const float*)d_in[4];
    const float* rec = (const float*)d_in[5];

    float* out     = (float*)d_out;
    float* y1_out  = out;
    float* hid_out = out + (size_t)MTOT * HIDN;

    __half *Ah, *Wh0, *Wh1, *linh;
    cudaGetSymbolAddress((void**)&Ah,   g_Ah);
    cudaGetSymbolAddress((void**)&Wh0,  g_Wh0);
    cudaGetSymbolAddress((void**)&Wh1,  g_Wh1);
    cudaGetSymbolAddress((void**)&linh, g_linh);

    cudaFuncSetAttribute(gemm_fp16, cudaFuncAttributeMaxDynamicSharedMemorySize, GEMM_SMEM);

    const int nX4 = MTOT * KDIM / 4;
    const int nW4 = HIDN * KDIM / 4;

    dim3 ggrid(HIDN / 128, MTOT / 128);  // (8, 64)
    dim3 sgrid(BH / 256);                // 128 blocks

    // All converts up-front (w1 convert no longer blocks the gemm0->scan0->gemm1 chain)
    cvt_fp32_fp16<<<(nW4 + 255) / 256, 256>>>(w0, Wh0, nW4);
    cvt_fp32_fp16<<<(nW4 + 255) / 256, 256>>>(w1, Wh1, nW4);
    cvt_fp32_fp16<<<(nX4 + 255) / 256, 256>>>(x, Ah, nX4);

    // Layer 0
    gemm_fp16<<<ggrid, 128, GEMM_SMEM>>>(Ah, Wh0, b0, linh);
    indrnn_scan_h<<<sgrid, 256>>>(linh, rec, Ah, hid_out, 0);

    // Layer 1
    gemm_fp16<<<ggrid, 128, GEMM_SMEM>>>(Ah, Wh1, b1, linh);
    indrnn_scan_f32<<<sgrid, 256>>>(linh, rec + HIDN, y1_out, hid_out, HIDN);
}